// round 10
// baseline (speedup 1.0000x reference)
#include <cuda_runtime.h>
#include <math.h>

#define N_PCD 5000
#define N_RGB 15000
#define NTOT  20000
#define NA    4096
#define SA_NS 32
#define NB_K  64
#define K1    163
#define NROWS (NA*SA_NS)

// FPS cluster config
#define FPS_CTAS    8
#define FPS_THREADS 512
#define FPS_SLICE   3072          // points per CTA
#define FPS_PPT     6             // points per thread
#define NPAD2       (FPS_CTAS*FPS_SLICE)   // 24576

// ---------------- static device scratch ----------------
__device__ float g_xs[NPAD2], g_ys[NPAD2], g_zs[NPAD2];
__device__ float g_ax[NA], g_ay[NA], g_az[NA];
__device__ int   g_fidx[NA];
__device__ int   g_nb[NA*SA_NS];
__device__ float g_rgbT[(size_t)N_RGB*128];
__device__ float g_W1T[K1*128];
__device__ float g_W2T[128*128];
__device__ float g_W3T[128*128];
__device__ float g_fpW1T[160*128];
__device__ float g_fpW2T[128*32];
__device__ float g_G [(size_t)NROWS*K1];
__device__ float g_H1[(size_t)NROWS*128];
__device__ float g_H2[(size_t)NROWS*128];
__device__ float g_saf[NA*128];
__device__ int   g_nn[N_PCD*3];
__device__ float g_wg[N_PCD*3];
__device__ float g_fpf[N_PCD*32];
__device__ int   g_nb2[N_PCD*NB_K];
__device__ unsigned int g_gmax;

// (dx*dx + dy*dy) + dz*dz, contraction forbidden (FMA could flip argmax/top-k ties)
__device__ __forceinline__ float sqdist(float ax, float ay, float az,
                                        float bx, float by, float bz) {
  float dx = __fadd_rn(ax, -bx);
  float dy = __fadd_rn(ay, -by);
  float dz = __fadd_rn(az, -bz);
  return __fadd_rn(__fadd_rn(__fmul_rn(dx,dx), __fmul_rn(dy,dy)), __fmul_rn(dz,dz));
}

// ---------------- PTX helpers (cluster DSMEM + mbarrier) ----------------
__device__ __forceinline__ unsigned su32(const void* p) {
  unsigned a;
  asm("{ .reg .u64 t; cvta.to.shared.u64 t, %1; cvt.u32.u64 %0, t; }" : "=r"(a) : "l"(p));
  return a;
}
__device__ __forceinline__ unsigned mapa_u32(unsigned a, unsigned r) {
  unsigned d; asm("mapa.shared::cluster.u32 %0, %1, %2;" : "=r"(d) : "r"(a), "r"(r));
  return d;
}
__device__ __forceinline__ void stc_f32(unsigned a, float v) {
  asm volatile("st.shared::cluster.f32 [%0], %1;" :: "r"(a), "f"(v) : "memory");
}
__device__ __forceinline__ void stc_u32(unsigned a, unsigned v) {
  asm volatile("st.shared::cluster.u32 [%0], %1;" :: "r"(a), "r"(v) : "memory");
}
__device__ __forceinline__ void mbar_init(unsigned a, unsigned c) {
  asm volatile("mbarrier.init.shared.b64 [%0], %1;" :: "r"(a), "r"(c) : "memory");
}
__device__ __forceinline__ void mbar_arrive_cl(unsigned a) {
  asm volatile("mbarrier.arrive.release.cluster.shared::cluster.b64 _, [%0];" :: "r"(a) : "memory");
}
__device__ __forceinline__ void mbar_wait(unsigned a, unsigned ph) {
  asm volatile("{\n\t.reg .pred P;\nW_%=:\n\t"
               "mbarrier.try_wait.parity.acquire.cluster.shared::cta.b64 P, [%0], %1, 0x989680;\n\t"
               "@P bra.uni D_%=;\n\tbra.uni W_%=;\nD_%=:\n}"
               :: "r"(a), "r"(ph) : "memory");
}
__device__ __forceinline__ void cluster_sync_all() {
  asm volatile("barrier.cluster.arrive.aligned;" ::: "memory");
  asm volatile("barrier.cluster.wait.aligned;" ::: "memory");
}

// ---------------- prep: SoA xyz (padded), seed FPS step 0 ----------------
__global__ void k_build(const float* __restrict__ pcd_xyz,
                        const float* __restrict__ rgb_xyz) {
  int i = blockIdx.x*blockDim.x + threadIdx.x;
  if (i == 0) {
    g_gmax = 0u;
    g_fidx[0] = 0;
    g_ax[0] = pcd_xyz[0]; g_ay[0] = pcd_xyz[1]; g_az[0] = pcd_xyz[2];
  }
  if (i >= NPAD2) return;
  float x=0.f, y=0.f, z=0.f;
  if (i < N_PCD)      { x=pcd_xyz[i*3]; y=pcd_xyz[i*3+1]; z=pcd_xyz[i*3+2]; }
  else if (i < NTOT)  { int j=i-N_PCD; x=rgb_xyz[j*3]; y=rgb_xyz[j*3+1]; z=rgb_xyz[j*3+2]; }
  g_xs[i]=x; g_ys[i]=y; g_zs[i]=z;
}

// ---------------- merged weight transposes ----------------
__global__ void k_transW(const float* __restrict__ sa_W1, const float* __restrict__ sa_W2,
                         const float* __restrict__ sa_W3, const float* __restrict__ fp_W1,
                         const float* __restrict__ fp_W2) {
  int i = blockIdx.x*blockDim.x + threadIdx.x;
  if (i < 163*128) { int k=i>>7, n=i&127; g_W1T[i] = sa_W1[n*163+k]; return; }
  i -= 163*128;
  if (i < 128*128) { int k=i>>7, n=i&127; g_W2T[i] = sa_W2[n*128+k]; return; }
  i -= 128*128;
  if (i < 128*128) { int k=i>>7, n=i&127; g_W3T[i] = sa_W3[n*128+k]; return; }
  i -= 128*128;
  if (i < 160*128) { int k=i>>7, n=i&127; g_fpW1T[i] = fp_W1[n*288+k]; return; } // cols>=160 hit zeros
  i -= 160*128;
  if (i < 128*32)  { int k=i>>5, n=i&31;  g_fpW2T[i] = fp_W2[n*128+k]; return; }
}

// ---------------- rgb feature transpose, smem-tiled (coalesced both ways) ----------------
__global__ void k_transRGB(const float* __restrict__ W) { // W: [128, 15000]
  __shared__ float tile[32][33];
  int kb = blockIdx.x * 32;
  int nb = blockIdx.y * 32;
  int tx = threadIdx.x, ty = threadIdx.y;   // 32 x 8
#pragma unroll
  for (int j = 0; j < 4; j++) {
    int n = nb + ty + j*8, k = kb + tx;
    tile[ty + j*8][tx] = (k < N_RGB) ? W[(size_t)n*N_RGB + k] : 0.f;
  }
  __syncthreads();
#pragma unroll
  for (int j = 0; j < 4; j++) {
    int k = kb + ty + j*8, n = nb + tx;
    if (k < N_RGB) g_rgbT[(size_t)k*128 + n] = tile[tx][ty + j*8];
  }
}

// ---------------- FPS: 8-CTA cluster, DSMEM gather/broadcast per step ----------------
__global__ __launch_bounds__(FPS_THREADS, 1) __cluster_dims__(FPS_CTAS, 1, 1)
void k_fps2() {
  __shared__ float2 sxy[FPS_SLICE];
  __shared__ float  szz[FPS_SLICE];
  __shared__ float  s_cv[FPS_CTAS];     // leader: candidate values
  __shared__ int    s_ci[FPS_CTAS];     // leader: candidate global indices
  __shared__ float  s_cx[FPS_CTAS], s_cy[FPS_CTAS], s_cz[FPS_CTAS];
  __shared__ float  s_center[3];
  __shared__ float  s_wval[16];
  __shared__ int    s_widx[16];
  __shared__ unsigned long long mb_gather;
  __shared__ unsigned long long mb_bcast;

  int t = threadIdx.x;
  int rank = blockIdx.x;
  int base = rank * FPS_SLICE;

  unsigned a_gather = su32(&mb_gather);
  unsigned a_bcast  = su32(&mb_bcast);
  unsigned a_cv = su32(s_cv), a_ci = su32(s_ci);
  unsigned a_cx = su32(s_cx), a_cy = su32(s_cy), a_cz = su32(s_cz);
  unsigned a_cen = su32(s_center);

  for (int l = t; l < FPS_SLICE; l += FPS_THREADS) {
    int gi = base + l;
    sxy[l] = make_float2(g_xs[gi], g_ys[gi]);
    szz[l] = g_zs[gi];
  }
  float d[FPS_PPT], z[FPS_PPT];
#pragma unroll
  for (int k = 0; k < FPS_PPT; k++) {
    int gi = base + k*FPS_THREADS + t;
    z[k] = g_zs[gi];
    d[k] = (gi < NTOT) ? 1e10f : -1.0f;     // pads never win (real d >= 0)
  }
  if (t == 0) {
    mbar_init(a_bcast, 1);
    if (rank == 0) mbar_init(a_gather, FPS_CTAS);
  }
  __syncthreads();
  cluster_sync_all();   // mbarrier inits visible cluster-wide before any remote arrive

  float lx = g_xs[0], ly = g_ys[0], lz = g_zs[0];   // center 0 = point 0

  for (int step = 1; step < NA; step++) {
    unsigned ph = (unsigned)(step - 1) & 1u;
    float best = -1e30f; int bidx = 0;
#pragma unroll
    for (int k = 0; k < FPS_PPT; k++) {
      int l = k*FPS_THREADS + t;
      float2 xy = sxy[l];
      float dd = sqdist(xy.x, xy.y, z[k], lx, ly, lz);
      dd = fminf(d[k], dd);
      d[k] = dd;
      if (dd > best) { best = dd; bidx = l; }  // ascending l per thread: first max kept
    }
#pragma unroll
    for (int off = 16; off; off >>= 1) {
      float v = __shfl_down_sync(0xffffffffu, best, off);
      int   j = __shfl_down_sync(0xffffffffu, bidx, off);
      if (v > best || (v == best && j < bidx)) { best = v; bidx = j; }
    }
    if ((t & 31) == 0) { s_wval[t>>5] = best; s_widx[t>>5] = bidx; }
    __syncthreads();
    if (t < 32) {
      best = (t < 16) ? s_wval[t] : -1e30f;
      bidx = (t < 16) ? s_widx[t] : 0x7fffffff;
#pragma unroll
      for (int off = 16; off; off >>= 1) {
        float v = __shfl_down_sync(0xffffffffu, best, off);
        int   j = __shfl_down_sync(0xffffffffu, bidx, off);
        if (v > best || (v == best && j < bidx)) { best = v; bidx = j; }
      }
      if (t == 0) {
        float2 xy = sxy[bidx]; float zz = szz[bidx];
        // send candidate (val, gidx, x, y, z) to leader slot [rank]
        stc_f32(mapa_u32(a_cv, 0) + rank*4, best);
        stc_u32(mapa_u32(a_ci, 0) + rank*4, (unsigned)(base + bidx));
        stc_f32(mapa_u32(a_cx, 0) + rank*4, xy.x);
        stc_f32(mapa_u32(a_cy, 0) + rank*4, xy.y);
        stc_f32(mapa_u32(a_cz, 0) + rank*4, zz);
        mbar_arrive_cl(mapa_u32(a_gather, 0));
        if (rank == 0) {
          mbar_wait(a_gather, ph);
          float bv = -1e30f; int bi = 0; float bx=0.f, by=0.f, bz=0.f;
#pragma unroll
          for (int r = 0; r < FPS_CTAS; r++) {   // ascending rank = ascending index range
            float v = s_cv[r];
            if (v > bv) { bv = v; bi = s_ci[r]; bx = s_cx[r]; by = s_cy[r]; bz = s_cz[r]; }
          }
          g_fidx[step] = bi; g_ax[step] = bx; g_ay[step] = by; g_az[step] = bz;
#pragma unroll
          for (int r = 0; r < FPS_CTAS; r++) {
            unsigned rc = mapa_u32(a_cen, r);
            stc_f32(rc + 0, bx); stc_f32(rc + 4, by); stc_f32(rc + 8, bz);
            mbar_arrive_cl(mapa_u32(a_bcast, r));
          }
        }
      }
    }
    mbar_wait(a_bcast, ph);
    lx = s_center[0]; ly = s_center[1]; lz = s_center[2];
  }
  cluster_sync_all();
}

// ---------------- ball query: first-k in-radius by INDEX, pad with first ----------------
__global__ void k_ballq(int mode) {
  int w    = (blockIdx.x*blockDim.x + threadIdx.x) >> 5;
  int lane = threadIdx.x & 31;
  int npoints, ks; float r2, cx, cy, cz; int* row;
  if (mode == 0) {
    if (w >= NA) return;
    npoints = NTOT; ks = SA_NS; r2 = 0.01f;       // f32(0.1*0.1)
    cx = g_ax[w]; cy = g_ay[w]; cz = g_az[w];
    row = g_nb + (size_t)w*SA_NS;
  } else {
    if (w >= N_PCD) return;
    npoints = N_PCD; ks = NB_K; r2 = 0.04f;       // f32(0.2*0.2)
    cx = g_xs[w]; cy = g_ys[w]; cz = g_zs[w];
    row = g_nb2 + (size_t)w*NB_K;
  }
  int cnt = 0;
  for (int bs = 0; bs < npoints && cnt < ks; bs += 32) {
    int i = bs + lane;
    bool in = false;
    if (i < npoints) {
      float dd = sqdist(g_xs[i], g_ys[i], g_zs[i], cx, cy, cz);
      in = dd < r2;
    }
    unsigned m = __ballot_sync(0xffffffffu, in);
    if (m) {
      int rnk = __popc(m & ((1u << lane) - 1u));
      int pos = cnt + rnk;
      if (in && pos < ks) row[pos] = i;
      cnt += __popc(m);
    }
  }
  __syncwarp();
  if (cnt < ks) {               // center always in-radius -> cnt >= 1
    int first = row[0];
    for (int j = cnt + lane; j < ks; j += 32) row[j] = first;
  }
}

// ---------------- gather G = [gxyz | pcd_feat | rgb_feat] ----------------
__global__ void k_gather(const float* __restrict__ pcd_feat) {
  int r = blockIdx.x;
  int t = threadIdx.x;
  if (t >= K1) return;
  int a = r >> 5;
  int p = g_nb[r];
  float v;
  if (t < 3) {
    float pc = (t == 0) ? g_xs[p] : (t == 1) ? g_ys[p] : g_zs[p];
    float ac = (t == 0) ? g_ax[a] : (t == 1) ? g_ay[a] : g_az[a];
    v = __fadd_rn(pc, -ac) / 0.1f;
  } else if (t < 35) {
    v = (p < N_PCD) ? pcd_feat[p*32 + (t-3)] : 0.f;
  } else {
    v = (p >= N_PCD) ? g_rgbT[(size_t)(p - N_PCD)*128 + (t-35)] : 0.f;
  }
  g_G[(size_t)r*K1 + t] = v;
}

// ---------------- SGEMM + bias + relu: M=131072, N=128 ----------------
__global__ void __launch_bounds__(256, 2)
k_gemm(int layer, const float* __restrict__ b1,
       const float* __restrict__ b2, const float* __restrict__ b3) {
  const float* A; const float* Bt; const float* bias; float* C; int K;
  if (layer == 0)      { A=g_G;  Bt=g_W1T; bias=b1; C=g_H1; K=K1;  }
  else if (layer == 1) { A=g_H1; Bt=g_W2T; bias=b2; C=g_H2; K=128; }
  else                 { A=g_H2; Bt=g_W3T; bias=b3; C=g_H1; K=128; }

  __shared__ float As[8*132];
  __shared__ float Bs[8*128];
  int t  = threadIdx.x;
  int m0 = blockIdx.x * 128;
  int ty = t >> 4, tx = t & 15;
  float acc[8][8];
#pragma unroll
  for (int r = 0; r < 8; r++)
#pragma unroll
    for (int c = 0; c < 8; c++) acc[r][c] = 0.f;

  for (int k0 = 0; k0 < K; k0 += 8) {
#pragma unroll
    for (int i = 0; i < 4; i++) {
      int idx = t + i*256;
      int ml = idx >> 3, kk = idx & 7;
      int kg = k0 + kk;
      As[kk*132 + ml] = (kg < K) ? A[(size_t)(m0+ml)*K + kg] : 0.f;
    }
#pragma unroll
    for (int i = 0; i < 4; i++) {
      int idx = t + i*256;
      int kk = idx >> 7, n = idx & 127;
      int kg = k0 + kk;
      Bs[kk*128 + n] = (kg < K) ? Bt[(size_t)kg*128 + n] : 0.f;
    }
    __syncthreads();
#pragma unroll
    for (int kk = 0; kk < 8; kk++) {
      float4 a0 = *(const float4*)&As[kk*132 + ty*8];
      float4 a1 = *(const float4*)&As[kk*132 + ty*8 + 4];
      float4 b0 = *(const float4*)&Bs[kk*128 + tx*8];
      float4 b1 = *(const float4*)&Bs[kk*128 + tx*8 + 4];
      float a[8] = {a0.x,a0.y,a0.z,a0.w,a1.x,a1.y,a1.z,a1.w};
      float b[8] = {b0.x,b0.y,b0.z,b0.w,b1.x,b1.y,b1.z,b1.w};
#pragma unroll
      for (int r = 0; r < 8; r++)
#pragma unroll
        for (int c = 0; c < 8; c++) acc[r][c] = fmaf(a[r], b[c], acc[r][c]);
    }
    __syncthreads();
  }
#pragma unroll
  for (int r = 0; r < 8; r++) {
    int m = m0 + ty*8 + r;
#pragma unroll
    for (int c = 0; c < 8; c++) {
      int n = tx*8 + c;
      float v = acc[r][c] + bias[n];
      C[(size_t)m*128 + n] = v > 0.f ? v : 0.f;
    }
  }
}

__global__ void k_maxpool() {
  int a = blockIdx.x, c = threadIdx.x;
  const float* base = g_H1 + (size_t)a*SA_NS*128 + c;
  float m = base[0];
#pragma unroll 4
  for (int s = 1; s < SA_NS; s++) m = fmaxf(m, base[(size_t)s*128]);
  g_saf[a*128 + c] = m;
}

// ---------------- 3-NN among anchors + inverse-distance weights ----------------
__global__ void k_nn3() {
  int i = blockIdx.x*blockDim.x + threadIdx.x;
  if (i >= N_PCD) return;
  float px = g_xs[i], py = g_ys[i], pz = g_zs[i];
  float d0 = 1e30f, d1 = 1e30f, d2 = 1e30f;
  int   i0 = 0, i1 = 0, i2 = 0;
  for (int a = 0; a < NA; a++) {
    float dd = sqdist(px, py, pz, g_ax[a], g_ay[a], g_az[a]);
    if (dd < d2) {                 // strict: earlier index wins ties (lax.top_k stable)
      if (dd < d1) {
        d2 = d1; i2 = i1;
        if (dd < d0) { d1 = d0; i1 = i0; d0 = dd; i0 = a; }
        else         { d1 = dd; i1 = a; }
      } else { d2 = dd; i2 = a; }
    }
  }
  float w0 = 1.0f/(d0 + 1e-8f), w1 = 1.0f/(d1 + 1e-8f), w2 = 1.0f/(d2 + 1e-8f);
  float ws = (w0 + w1) + w2;
  g_nn[i*3+0]=i0; g_nn[i*3+1]=i1; g_nn[i*3+2]=i2;
  g_wg[i*3+0]=w0/ws; g_wg[i*3+1]=w1/ws; g_wg[i*3+2]=w2/ws;
}

// ---------------- fused FP MLP (5000 pcd rows; effective K=160) ----------------
__global__ void k_fp(const float* __restrict__ pcd_feat,
                     const float* __restrict__ b1, const float* __restrict__ b2,
                     float* __restrict__ out_vf) {
  __shared__ float s_in[128];
  __shared__ float s_pf[32];
  __shared__ float s_h[128];
  int n = blockIdx.x, t = threadIdx.x;
  int i0 = g_nn[n*3+0], i1 = g_nn[n*3+1], i2 = g_nn[n*3+2];
  float w0 = g_wg[n*3+0], w1 = g_wg[n*3+1], w2 = g_wg[n*3+2];
  s_in[t] = w0*g_saf[i0*128+t] + w1*g_saf[i1*128+t] + w2*g_saf[i2*128+t];
  if (t < 32) s_pf[t] = pcd_feat[n*32 + t];
  __syncthreads();
  float acc = b1[t];
#pragma unroll 8
  for (int k = 0; k < 128; k++) acc = fmaf(s_in[k], g_fpW1T[k*128 + t], acc);
#pragma unroll 8
  for (int k = 0; k < 32; k++)  acc = fmaf(s_pf[k], g_fpW1T[(128+k)*128 + t], acc);
  s_h[t] = acc > 0.f ? acc : 0.f;
  __syncthreads();
  if (t < 32) {
    float a2 = b2[t];
#pragma unroll 8
    for (int k = 0; k < 128; k++) a2 = fmaf(s_h[k], g_fpW2T[k*32 + t], a2);
    float v = a2 > 0.f ? a2 : 0.f;
    g_fpf[n*32 + t] = v;
    atomicMax(&g_gmax, __float_as_uint(v));     // relu>=0 -> uint order == float order
    float sq = v*v;
#pragma unroll
    for (int off = 16; off; off >>= 1) sq += __shfl_xor_sync(0xffffffffu, sq, off);
    float nrm = fmaxf(sqrtf(sq), 1e-12f);
    out_vf[n*32 + t] = v / nrm;
  }
}

// ---------------- detection scores ----------------
__global__ void k_det(float* __restrict__ out_scores) {
  int i = blockIdx.x, c = threadIdx.x;   // 32 threads = 32 channels
  const int* nb = g_nb2 + (size_t)i*NB_K;
  float sum = 0.f;
#pragma unroll 4
  for (int j = 0; j < NB_K; j++) sum += g_fpf[nb[j]*32 + c];
  float s = __uint_as_float(g_gmax) + 1e-6f;
  float fi = g_fpf[i*32 + c] / s;
  float mean = (sum * (1.0f/64.0f)) / s;
  float x = fi - mean;
  float lm = fmaxf(x, 0.f) + log1pf(expf(-fabsf(x)));   // softplus
  float dwmax = fi;
#pragma unroll
  for (int off = 16; off; off >>= 1) dwmax = fmaxf(dwmax, __shfl_xor_sync(0xffffffffu, dwmax, off));
  float sc = lm * (fi / (1e-6f + dwmax));
#pragma unroll
  for (int off = 16; off; off >>= 1) sc = fmaxf(sc, __shfl_xor_sync(0xffffffffu, sc, off));
  if (c == 0) out_scores[i] = sc;
}

__global__ void k_out(const float* __restrict__ pcd_xyz, float* __restrict__ out) {
  int i = blockIdx.x*blockDim.x + threadIdx.x;
  if (i < N_PCD*3) out[i] = pcd_xyz[i];
}

extern "C" void kernel_launch(void* const* d_in, const int* in_sizes, int n_in,
                              void* d_out, int out_size) {
  (void)in_sizes; (void)n_in; (void)out_size;
  const float* pcd_xyz   = (const float*)d_in[0];
  const float* pcd_feat  = (const float*)d_in[1];
  const float* rgb_xyz   = (const float*)d_in[2];
  const float* rgb_feats = (const float*)d_in[3];
  const float* sa_W1 = (const float*)d_in[4];
  const float* sa_b1 = (const float*)d_in[5];
  const float* sa_W2 = (const float*)d_in[6];
  const float* sa_b2 = (const float*)d_in[7];
  const float* sa_W3 = (const float*)d_in[8];
  const float* sa_b3 = (const float*)d_in[9];
  const float* fp_W1 = (const float*)d_in[10];
  const float* fp_b1 = (const float*)d_in[11];
  const float* fp_W2 = (const float*)d_in[12];
  const float* fp_b2 = (const float*)d_in[13];
  float* out = (float*)d_out;
  float* out_scores = out + N_PCD*3;          // 15000..20000
  float* out_vf     = out + N_PCD*3 + N_PCD;  // 20000..180000

  k_build<<<(NPAD2+255)/256, 256>>>(pcd_xyz, rgb_xyz);
  k_transW<<<(78208+255)/256, 256>>>(sa_W1, sa_W2, sa_W3, fp_W1, fp_W2);
  { dim3 g((N_RGB+31)/32, 4), b(32, 8); k_transRGB<<<g, b>>>(rgb_feats); }
  k_fps2<<<FPS_CTAS, FPS_THREADS>>>();
  k_ballq<<<(NA*32+255)/256, 256>>>(0);
  k_gather<<<NROWS, 192>>>(pcd_feat);
  k_gemm<<<NROWS/128, 256>>>(0, sa_b1, sa_b2, sa_b3);
  k_gemm<<<NROWS/128, 256>>>(1, sa_b1, sa_b2, sa_b3);
  k_gemm<<<NROWS/128, 256>>>(2, sa_b1, sa_b2, sa_b3);
  k_maxpool<<<NA, 128>>>();
  k_nn3<<<(N_PCD+255)/256, 256>>>();
  k_fp<<<N_PCD, 128>>>(pcd_feat, fp_b1, fp_b2, out_vf);
  k_ballq<<<(N_PCD*32+255)/256, 256>>>(1);
  k_det<<<N_PCD, 32>>>(out_scores);
  k_out<<<(N_PCD*3+255)/256, 256>>>(pcd_xyz, out);
}

// round 11
// speedup vs baseline: 1.6550x; 1.6550x over previous
#include <cuda_runtime.h>
#include <math.h>

#define N_PCD 5000
#define N_RGB 15000
#define NTOT  20000
#define NA    4096
#define SA_NS 32
#define NB_K  64
#define K1    163
#define NROWS (NA*SA_NS)
#define NCELL 512
#define CELL_R 0.10830f   /* > sqrt(3)/16 = 0.108253: conservative half-diagonal */

// ---------------- static device scratch ----------------
__device__ float g_xs[NTOT], g_ys[NTOT], g_zs[NTOT];
__device__ float g_ax[NA], g_ay[NA], g_az[NA];
__device__ int   g_nb[NA*SA_NS];
__device__ float g_rgbT[(size_t)N_RGB*128];
__device__ float g_W1T[K1*128];
__device__ float g_W2T[128*128];
__device__ float g_W3T[128*128];
__device__ float g_fpW1T[160*128];
__device__ float g_fpW2T[128*32];
__device__ float g_G [(size_t)NROWS*K1];
__device__ float g_H1[(size_t)NROWS*128];
__device__ float g_H2[(size_t)NROWS*128];
__device__ float g_saf[NA*128];
__device__ int   g_nn[N_PCD*3];
__device__ float g_wg[N_PCD*3];
__device__ float g_fpf[N_PCD*32];
__device__ int   g_nb2[N_PCD*NB_K];
__device__ unsigned int g_gmax;
// FPS cell structures
__device__ float4 g_sp[NTOT];          // sorted (x,y,z,orig-as-float-bits)
__device__ float  g_sd[NTOT];          // running min sq-dist (sorted order)
__device__ int    g_cid[NTOT];
__device__ int    g_ccnt[NCELL];
__device__ int    g_cstart[NCELL+1];
__device__ int    g_cfill[NCELL];

// (dx*dx + dy*dy) + dz*dz, contraction forbidden (FMA could flip argmax/top-k ties)
__device__ __forceinline__ float sqdist(float ax, float ay, float az,
                                        float bx, float by, float bz) {
  float dx = __fadd_rn(ax, -bx);
  float dy = __fadd_rn(ay, -by);
  float dz = __fadd_rn(az, -bz);
  return __fadd_rn(__fadd_rn(__fmul_rn(dx,dx), __fmul_rn(dy,dy)), __fmul_rn(dz,dz));
}

// ---------------- prep: SoA xyz, zero cell counts, seed FPS step 0 ----------------
__global__ void k_build(const float* __restrict__ pcd_xyz,
                        const float* __restrict__ rgb_xyz) {
  int i = blockIdx.x*blockDim.x + threadIdx.x;
  if (i == 0) {
    g_gmax = 0u;
    g_ax[0] = pcd_xyz[0]; g_ay[0] = pcd_xyz[1]; g_az[0] = pcd_xyz[2];
  }
  if (i < NCELL) g_ccnt[i] = 0;
  if (i >= NTOT) return;
  float x, y, z;
  if (i < N_PCD) { x=pcd_xyz[i*3]; y=pcd_xyz[i*3+1]; z=pcd_xyz[i*3+2]; }
  else           { int j=i-N_PCD; x=rgb_xyz[j*3]; y=rgb_xyz[j*3+1]; z=rgb_xyz[j*3+2]; }
  g_xs[i]=x; g_ys[i]=y; g_zs[i]=z;
}

__device__ __forceinline__ int cell_of(float x, float y, float z) {
  int ix = min(7, max(0, (int)(x * 8.0f)));
  int iy = min(7, max(0, (int)(y * 8.0f)));
  int iz = min(7, max(0, (int)(z * 8.0f)));
  return (iz*8 + iy)*8 + ix;
}

__global__ void k_cellidx() {
  int i = blockIdx.x*blockDim.x + threadIdx.x;
  if (i >= NTOT) return;
  int c = cell_of(g_xs[i], g_ys[i], g_zs[i]);
  g_cid[i] = c;
  atomicAdd(&g_ccnt[c], 1);
}

__global__ void k_cellscan() {   // one block, 512 threads: exclusive scan
  __shared__ int s[NCELL];
  int t = threadIdx.x;
  int x = g_ccnt[t];
  s[t] = x;
  __syncthreads();
  for (int o = 1; o < NCELL; o <<= 1) {
    int u = (t >= o) ? s[t-o] : 0;
    __syncthreads();
    s[t] += u;
    __syncthreads();
  }
  int start = s[t] - x;
  g_cstart[t] = start;
  g_cfill[t]  = start;
  if (t == NCELL-1) g_cstart[NCELL] = s[t];
}

__global__ void k_scatter() {
  int i = blockIdx.x*blockDim.x + threadIdx.x;
  if (i >= NTOT) return;
  int c = g_cid[i];
  int pos = atomicAdd(&g_cfill[c], 1);
  g_sp[pos] = make_float4(g_xs[i], g_ys[i], g_zs[i], __int_as_float(i));
  g_sd[pos] = 1e10f;
}

// ---------------- merged weight transposes ----------------
__global__ void k_transW(const float* __restrict__ sa_W1, const float* __restrict__ sa_W2,
                         const float* __restrict__ sa_W3, const float* __restrict__ fp_W1,
                         const float* __restrict__ fp_W2) {
  int i = blockIdx.x*blockDim.x + threadIdx.x;
  if (i < 163*128) { int k=i>>7, n=i&127; g_W1T[i] = sa_W1[n*163+k]; return; }
  i -= 163*128;
  if (i < 128*128) { int k=i>>7, n=i&127; g_W2T[i] = sa_W2[n*128+k]; return; }
  i -= 128*128;
  if (i < 128*128) { int k=i>>7, n=i&127; g_W3T[i] = sa_W3[n*128+k]; return; }
  i -= 128*128;
  if (i < 160*128) { int k=i>>7, n=i&127; g_fpW1T[i] = fp_W1[n*288+k]; return; } // cols>=160 hit zeros
  i -= 160*128;
  if (i < 128*32)  { int k=i>>5, n=i&31;  g_fpW2T[i] = fp_W2[n*128+k]; return; }
}

// ---------------- rgb feature transpose, smem-tiled ----------------
__global__ void k_transRGB(const float* __restrict__ W) { // W: [128, 15000]
  __shared__ float tile[32][33];
  int kb = blockIdx.x * 32;
  int nb = blockIdx.y * 32;
  int tx = threadIdx.x, ty = threadIdx.y;   // 32 x 8
#pragma unroll
  for (int j = 0; j < 4; j++) {
    int n = nb + ty + j*8, k = kb + tx;
    tile[ty + j*8][tx] = (k < N_RGB) ? W[(size_t)n*N_RGB + k] : 0.f;
  }
  __syncthreads();
#pragma unroll
  for (int j = 0; j < 4; j++) {
    int k = kb + ty + j*8, n = nb + tx;
    if (k < N_RGB) g_rgbT[(size_t)k*128 + n] = tile[tx][ty + j*8];
  }
}

// ---------------- FPS: single block + spatial-cell triangle-inequality pruning ----------------
__global__ void __launch_bounds__(1024, 1) k_fps3() {
  __shared__ float s_dmax[NCELL];      // per-cell max of current d
  __shared__ int   s_dorig[NCELL];     // original index of that max
  __shared__ float s_mx[NCELL], s_my[NCELL], s_mz[NCELL];  // coords of that max
  __shared__ int   s_start[NCELL+1];
  __shared__ int   s_active[NCELL];
  __shared__ int   s_nact;
  __shared__ int   s_wcnt[16], s_woff[16];
  __shared__ float s_center[3];
  __shared__ float s_rv[16]; __shared__ int s_ro[16], s_rc[16];

  int t = threadIdx.x;
  int lane = t & 31, w = t >> 5;
  if (t <= NCELL) s_start[t] = g_cstart[t];
  __syncthreads();
  if (t < NCELL) {
    int cnt = s_start[t+1] - s_start[t];
    s_dmax[t]  = (cnt > 0) ? 1e10f : -1e30f;   // empty cells never win
    s_dorig[t] = 0x7fffffff;
    s_mx[t]=0.f; s_my[t]=0.f; s_mz[t]=0.f;
  }
  if (t == 0) { s_center[0]=g_ax[0]; s_center[1]=g_ay[0]; s_center[2]=g_az[0]; }
  __syncthreads();

  for (int step = 1; step < NA; step++) {
    float cx = s_center[0], cy = s_center[1], cz = s_center[2];

    // Phase A: prune test + compaction (warps 0..15)
    bool act = false; int off = 0;
    if (t < NCELL) {
      int cnt = s_start[t+1] - s_start[t];
      if (cnt > 0) {
        int ix = t & 7, iy = (t >> 3) & 7, iz = t >> 6;
        float dc2 = sqdist((ix+0.5f)*0.125f, (iy+0.5f)*0.125f, (iz+0.5f)*0.125f,
                           cx, cy, cz);
        float lb = __fsqrt_rn(dc2) - CELL_R;
        // skip only when PROVABLY every point's new dist^2 exceeds its current d
        act = !(lb > 0.f && __fmul_rn(lb, lb) * 0.9999f > s_dmax[t]);
      }
      unsigned m = __ballot_sync(0xffffffffu, act);
      if (lane == 0) s_wcnt[w] = __popc(m);
      off = __popc(m & ((1u << lane) - 1u));
    }
    __syncthreads();
    if (t == 0) {
      int s = 0;
#pragma unroll
      for (int i = 0; i < 16; i++) { s_woff[i] = s; s += s_wcnt[i]; }
      s_nact = s;
    }
    __syncthreads();
    if (t < NCELL && act) s_active[s_woff[w] + off] = t;
    __syncthreads();

    // Phase B: update active cells (all 32 warps, strided over active list)
    int nact = s_nact;
    for (int j = w; j < nact; j += 32) {
      int cell = s_active[j];
      int st = s_start[cell], en = s_start[cell+1];
      float bv = -1e30f; int borig = 0x7fffffff; float bx=0.f, by=0.f, bz=0.f;
      for (int p0 = st; p0 < en; p0 += 32) {
        int p = p0 + lane;
        float v = -1e30f; int orig = 0x7fffffff; float x=0.f, y=0.f, z=0.f;
        if (p < en) {
          float4 q = g_sp[p];
          x = q.x; y = q.y; z = q.z; orig = __float_as_int(q.w);
          float dd = sqdist(x, y, z, cx, cy, cz);
          float nd = fminf(g_sd[p], dd);
          g_sd[p] = nd;
          v = nd;
        }
        if (v > bv || (v == bv && orig < borig)) { bv=v; borig=orig; bx=x; by=y; bz=z; }
      }
#pragma unroll
      for (int o = 16; o; o >>= 1) {
        float v = __shfl_down_sync(0xffffffffu, bv, o);
        int   g = __shfl_down_sync(0xffffffffu, borig, o);
        float X = __shfl_down_sync(0xffffffffu, bx, o);
        float Y = __shfl_down_sync(0xffffffffu, by, o);
        float Z = __shfl_down_sync(0xffffffffu, bz, o);
        if (v > bv || (v == bv && g < borig)) { bv=v; borig=g; bx=X; by=Y; bz=Z; }
      }
      if (lane == 0) {
        s_dmax[cell]=bv; s_dorig[cell]=borig;
        s_mx[cell]=bx; s_my[cell]=by; s_mz[cell]=bz;
      }
    }
    __syncthreads();

    // Phase C: argmax over 512 cells, tie-break by smallest original index
    if (t < NCELL) {
      float v = s_dmax[t]; int orig = s_dorig[t]; int cell = t;
#pragma unroll
      for (int o = 16; o; o >>= 1) {
        float vv = __shfl_down_sync(0xffffffffu, v, o);
        int   gg = __shfl_down_sync(0xffffffffu, orig, o);
        int   cc = __shfl_down_sync(0xffffffffu, cell, o);
        if (vv > v || (vv == v && gg < orig)) { v = vv; orig = gg; cell = cc; }
      }
      if (lane == 0) { s_rv[w] = v; s_ro[w] = orig; s_rc[w] = cell; }
    }
    __syncthreads();
    if (t < 32) {
      float v = (t < 16) ? s_rv[t] : -1e30f;
      int orig = (t < 16) ? s_ro[t] : 0x7fffffff;
      int cell = (t < 16) ? s_rc[t] : 0;
#pragma unroll
      for (int o = 16; o; o >>= 1) {
        float vv = __shfl_down_sync(0xffffffffu, v, o);
        int   gg = __shfl_down_sync(0xffffffffu, orig, o);
        int   cc = __shfl_down_sync(0xffffffffu, cell, o);
        if (vv > v || (vv == v && gg < orig)) { v = vv; orig = gg; cell = cc; }
      }
      if (t == 0) {
        float bx = s_mx[cell], by = s_my[cell], bz = s_mz[cell];
        s_center[0]=bx; s_center[1]=by; s_center[2]=bz;
        g_ax[step]=bx; g_ay[step]=by; g_az[step]=bz;
      }
    }
    __syncthreads();
  }
}

// ---------------- ball query: first-k in-radius by INDEX, pad with first ----------------
__global__ void k_ballq(int mode) {
  int w    = (blockIdx.x*blockDim.x + threadIdx.x) >> 5;
  int lane = threadIdx.x & 31;
  int npoints, ks; float r2, cx, cy, cz; int* row;
  if (mode == 0) {
    if (w >= NA) return;
    npoints = NTOT; ks = SA_NS; r2 = 0.01f;       // f32(0.1*0.1)
    cx = g_ax[w]; cy = g_ay[w]; cz = g_az[w];
    row = g_nb + (size_t)w*SA_NS;
  } else {
    if (w >= N_PCD) return;
    npoints = N_PCD; ks = NB_K; r2 = 0.04f;       // f32(0.2*0.2)
    cx = g_xs[w]; cy = g_ys[w]; cz = g_zs[w];
    row = g_nb2 + (size_t)w*NB_K;
  }
  int cnt = 0;
  for (int bs = 0; bs < npoints && cnt < ks; bs += 32) {
    int i = bs + lane;
    bool in = false;
    if (i < npoints) {
      float dd = sqdist(g_xs[i], g_ys[i], g_zs[i], cx, cy, cz);
      in = dd < r2;
    }
    unsigned m = __ballot_sync(0xffffffffu, in);
    if (m) {
      int rnk = __popc(m & ((1u << lane) - 1u));
      int pos = cnt + rnk;
      if (in && pos < ks) row[pos] = i;
      cnt += __popc(m);
    }
  }
  __syncwarp();
  if (cnt < ks) {               // center always in-radius -> cnt >= 1
    int first = row[0];
    for (int j = cnt + lane; j < ks; j += 32) row[j] = first;
  }
}

// ---------------- gather G = [gxyz | pcd_feat | rgb_feat] ----------------
__global__ void k_gather(const float* __restrict__ pcd_feat) {
  int r = blockIdx.x;
  int t = threadIdx.x;
  if (t >= K1) return;
  int a = r >> 5;
  int p = g_nb[r];
  float v;
  if (t < 3) {
    float pc = (t == 0) ? g_xs[p] : (t == 1) ? g_ys[p] : g_zs[p];
    float ac = (t == 0) ? g_ax[a] : (t == 1) ? g_ay[a] : g_az[a];
    v = __fadd_rn(pc, -ac) / 0.1f;
  } else if (t < 35) {
    v = (p < N_PCD) ? pcd_feat[p*32 + (t-3)] : 0.f;
  } else {
    v = (p >= N_PCD) ? g_rgbT[(size_t)(p - N_PCD)*128 + (t-35)] : 0.f;
  }
  g_G[(size_t)r*K1 + t] = v;
}

// ---------------- SGEMM + bias + relu: M=131072, N=128 ----------------
__global__ void __launch_bounds__(256, 2)
k_gemm(int layer, const float* __restrict__ b1,
       const float* __restrict__ b2, const float* __restrict__ b3) {
  const float* A; const float* Bt; const float* bias; float* C; int K;
  if (layer == 0)      { A=g_G;  Bt=g_W1T; bias=b1; C=g_H1; K=K1;  }
  else if (layer == 1) { A=g_H1; Bt=g_W2T; bias=b2; C=g_H2; K=128; }
  else                 { A=g_H2; Bt=g_W3T; bias=b3; C=g_H1; K=128; }

  __shared__ float As[8*132];
  __shared__ float Bs[8*128];
  int t  = threadIdx.x;
  int m0 = blockIdx.x * 128;
  int ty = t >> 4, tx = t & 15;
  float acc[8][8];
#pragma unroll
  for (int r = 0; r < 8; r++)
#pragma unroll
    for (int c = 0; c < 8; c++) acc[r][c] = 0.f;

  for (int k0 = 0; k0 < K; k0 += 8) {
#pragma unroll
    for (int i = 0; i < 4; i++) {
      int idx = t + i*256;
      int ml = idx >> 3, kk = idx & 7;
      int kg = k0 + kk;
      As[kk*132 + ml] = (kg < K) ? A[(size_t)(m0+ml)*K + kg] : 0.f;
    }
#pragma unroll
    for (int i = 0; i < 4; i++) {
      int idx = t + i*256;
      int kk = idx >> 7, n = idx & 127;
      int kg = k0 + kk;
      Bs[kk*128 + n] = (kg < K) ? Bt[(size_t)kg*128 + n] : 0.f;
    }
    __syncthreads();
#pragma unroll
    for (int kk = 0; kk < 8; kk++) {
      float4 a0 = *(const float4*)&As[kk*132 + ty*8];
      float4 a1 = *(const float4*)&As[kk*132 + ty*8 + 4];
      float4 b0 = *(const float4*)&Bs[kk*128 + tx*8];
      float4 b1 = *(const float4*)&Bs[kk*128 + tx*8 + 4];
      float a[8] = {a0.x,a0.y,a0.z,a0.w,a1.x,a1.y,a1.z,a1.w};
      float b[8] = {b0.x,b0.y,b0.z,b0.w,b1.x,b1.y,b1.z,b1.w};
#pragma unroll
      for (int r = 0; r < 8; r++)
#pragma unroll
        for (int c = 0; c < 8; c++) acc[r][c] = fmaf(a[r], b[c], acc[r][c]);
    }
    __syncthreads();
  }
#pragma unroll
  for (int r = 0; r < 8; r++) {
    int m = m0 + ty*8 + r;
#pragma unroll
    for (int c = 0; c < 8; c++) {
      int n = tx*8 + c;
      float v = acc[r][c] + bias[n];
      C[(size_t)m*128 + n] = v > 0.f ? v : 0.f;
    }
  }
}

__global__ void k_maxpool() {
  int a = blockIdx.x, c = threadIdx.x;
  const float* base = g_H1 + (size_t)a*SA_NS*128 + c;
  float m = base[0];
#pragma unroll 4
  for (int s = 1; s < SA_NS; s++) m = fmaxf(m, base[(size_t)s*128]);
  g_saf[a*128 + c] = m;
}

// ---------------- 3-NN among anchors + inverse-distance weights ----------------
__global__ void k_nn3() {
  int i = blockIdx.x*blockDim.x + threadIdx.x;
  if (i >= N_PCD) return;
  float px = g_xs[i], py = g_ys[i], pz = g_zs[i];
  float d0 = 1e30f, d1 = 1e30f, d2 = 1e30f;
  int   i0 = 0, i1 = 0, i2 = 0;
  for (int a = 0; a < NA; a++) {
    float dd = sqdist(px, py, pz, g_ax[a], g_ay[a], g_az[a]);
    if (dd < d2) {                 // strict: earlier index wins ties (lax.top_k stable)
      if (dd < d1) {
        d2 = d1; i2 = i1;
        if (dd < d0) { d1 = d0; i1 = i0; d0 = dd; i0 = a; }
        else         { d1 = dd; i1 = a; }
      } else { d2 = dd; i2 = a; }
    }
  }
  float w0 = 1.0f/(d0 + 1e-8f), w1 = 1.0f/(d1 + 1e-8f), w2 = 1.0f/(d2 + 1e-8f);
  float ws = (w0 + w1) + w2;
  g_nn[i*3+0]=i0; g_nn[i*3+1]=i1; g_nn[i*3+2]=i2;
  g_wg[i*3+0]=w0/ws; g_wg[i*3+1]=w1/ws; g_wg[i*3+2]=w2/ws;
}

// ---------------- fused FP MLP (5000 pcd rows; effective K=160) ----------------
__global__ void k_fp(const float* __restrict__ pcd_feat,
                     const float* __restrict__ b1, const float* __restrict__ b2,
                     float* __restrict__ out_vf) {
  __shared__ float s_in[128];
  __shared__ float s_pf[32];
  __shared__ float s_h[128];
  int n = blockIdx.x, t = threadIdx.x;
  int i0 = g_nn[n*3+0], i1 = g_nn[n*3+1], i2 = g_nn[n*3+2];
  float w0 = g_wg[n*3+0], w1 = g_wg[n*3+1], w2 = g_wg[n*3+2];
  s_in[t] = w0*g_saf[i0*128+t] + w1*g_saf[i1*128+t] + w2*g_saf[i2*128+t];
  if (t < 32) s_pf[t] = pcd_feat[n*32 + t];
  __syncthreads();
  float acc = b1[t];
#pragma unroll 8
  for (int k = 0; k < 128; k++) acc = fmaf(s_in[k], g_fpW1T[k*128 + t], acc);
#pragma unroll 8
  for (int k = 0; k < 32; k++)  acc = fmaf(s_pf[k], g_fpW1T[(128+k)*128 + t], acc);
  s_h[t] = acc > 0.f ? acc : 0.f;
  __syncthreads();
  if (t < 32) {
    float a2 = b2[t];
#pragma unroll 8
    for (int k = 0; k < 128; k++) a2 = fmaf(s_h[k], g_fpW2T[k*32 + t], a2);
    float v = a2 > 0.f ? a2 : 0.f;
    g_fpf[n*32 + t] = v;
    atomicMax(&g_gmax, __float_as_uint(v));     // relu>=0 -> uint order == float order
    float sq = v*v;
#pragma unroll
    for (int off = 16; off; off >>= 1) sq += __shfl_xor_sync(0xffffffffu, sq, off);
    float nrm = fmaxf(sqrtf(sq), 1e-12f);
    out_vf[n*32 + t] = v / nrm;
  }
}

// ---------------- detection scores ----------------
__global__ void k_det(float* __restrict__ out_scores) {
  int i = blockIdx.x, c = threadIdx.x;   // 32 threads = 32 channels
  const int* nb = g_nb2 + (size_t)i*NB_K;
  float sum = 0.f;
#pragma unroll 4
  for (int j = 0; j < NB_K; j++) sum += g_fpf[nb[j]*32 + c];
  float s = __uint_as_float(g_gmax) + 1e-6f;
  float fi = g_fpf[i*32 + c] / s;
  float mean = (sum * (1.0f/64.0f)) / s;
  float x = fi - mean;
  float lm = fmaxf(x, 0.f) + log1pf(expf(-fabsf(x)));   // softplus
  float dwmax = fi;
#pragma unroll
  for (int off = 16; off; off >>= 1) dwmax = fmaxf(dwmax, __shfl_xor_sync(0xffffffffu, dwmax, off));
  float sc = lm * (fi / (1e-6f + dwmax));
#pragma unroll
  for (int off = 16; off; off >>= 1) sc = fmaxf(sc, __shfl_xor_sync(0xffffffffu, sc, off));
  if (c == 0) out_scores[i] = sc;
}

__global__ void k_out(const float* __restrict__ pcd_xyz, float* __restrict__ out) {
  int i = blockIdx.x*blockDim.x + threadIdx.x;
  if (i < N_PCD*3) out[i] = pcd_xyz[i];
}

extern "C" void kernel_launch(void* const* d_in, const int* in_sizes, int n_in,
                              void* d_out, int out_size) {
  (void)in_sizes; (void)n_in; (void)out_size;
  const float* pcd_xyz   = (const float*)d_in[0];
  const float* pcd_feat  = (const float*)d_in[1];
  const float* rgb_xyz   = (const float*)d_in[2];
  const float* rgb_feats = (const float*)d_in[3];
  const float* sa_W1 = (const float*)d_in[4];
  const float* sa_b1 = (const float*)d_in[5];
  const float* sa_W2 = (const float*)d_in[6];
  const float* sa_b2 = (const float*)d_in[7];
  const float* sa_W3 = (const float*)d_in[8];
  const float* sa_b3 = (const float*)d_in[9];
  const float* fp_W1 = (const float*)d_in[10];
  const float* fp_b1 = (const float*)d_in[11];
  const float* fp_W2 = (const float*)d_in[12];
  const float* fp_b2 = (const float*)d_in[13];
  float* out = (float*)d_out;
  float* out_scores = out + N_PCD*3;          // 15000..20000
  float* out_vf     = out + N_PCD*3 + N_PCD;  // 20000..180000

  k_build<<<(NTOT+255)/256, 256>>>(pcd_xyz, rgb_xyz);          // 0
  k_cellidx<<<(NTOT+255)/256, 256>>>();                         // 1
  k_cellscan<<<1, NCELL>>>();                                   // 2
  k_scatter<<<(NTOT+255)/256, 256>>>();                         // 3
  k_transW<<<(78208+255)/256, 256>>>(sa_W1, sa_W2, sa_W3, fp_W1, fp_W2); // 4
  k_fps3<<<1, 1024>>>();                                        // 5 (ncu -s 5 lands here)
  { dim3 g((N_RGB+31)/32, 4), b(32, 8); k_transRGB<<<g, b>>>(rgb_feats); }
  k_ballq<<<(NA*32+255)/256, 256>>>(0);
  k_gather<<<NROWS, 192>>>(pcd_feat);
  k_gemm<<<NROWS/128, 256>>>(0, sa_b1, sa_b2, sa_b3);
  k_gemm<<<NROWS/128, 256>>>(1, sa_b1, sa_b2, sa_b3);
  k_gemm<<<NROWS/128, 256>>>(2, sa_b1, sa_b2, sa_b3);
  k_maxpool<<<NA, 128>>>();
  k_nn3<<<(N_PCD+255)/256, 256>>>();
  k_fp<<<N_PCD, 128>>>(pcd_feat, fp_b1, fp_b2, out_vf);
  k_ballq<<<(N_PCD*32+255)/256, 256>>>(1);
  k_det<<<N_PCD, 32>>>(out_scores);
  k_out<<<(N_PCD*3+255)/256, 256>>>(pcd_xyz, out);
}

// round 12
// speedup vs baseline: 2.1552x; 1.3022x over previous
#include <cuda_runtime.h>
#include <math.h>

#define N_PCD 5000
#define N_RGB 15000
#define NTOT  20000
#define NA    4096
#define SA_NS 32
#define NB_K  64
#define K1    163
#define NROWS (NA*SA_NS)
#define NCELL 512
#define CELL_R 0.10830f   /* > sqrt(3)/16 = 0.108253: conservative half-diagonal */

// ---------------- static device scratch ----------------
__device__ float g_xs[NTOT], g_ys[NTOT], g_zs[NTOT];
__device__ float g_ax[NA], g_ay[NA], g_az[NA];
__device__ int   g_nb[NA*SA_NS];
__device__ float g_rgbT[(size_t)N_RGB*128];
__device__ float g_W1T[K1*128];
__device__ float g_W2T[128*128];
__device__ float g_W3T[128*128];
__device__ float g_fpW1T[160*128];
__device__ float g_fpW2T[128*32];
__device__ float g_G [(size_t)NROWS*K1];
__device__ float g_H1[(size_t)NROWS*128];
__device__ float g_H2[(size_t)NROWS*128];
__device__ float g_saf[NA*128];
__device__ int   g_nn[N_PCD*3];
__device__ float g_wg[N_PCD*3];
__device__ float g_fpf[N_PCD*32];
__device__ int   g_nb2[N_PCD*NB_K];
__device__ unsigned int g_gmax;
// FPS cell structures
__device__ float4 g_sp[NTOT];          // sorted (x,y,z,orig-as-float-bits)
__device__ int    g_cid[NTOT];
__device__ int    g_ccnt[NCELL];
__device__ int    g_cstart[NCELL+1];
__device__ int    g_cfill[NCELL];

// (dx*dx + dy*dy) + dz*dz, contraction forbidden (FMA could flip argmax/top-k ties)
__device__ __forceinline__ float sqdist(float ax, float ay, float az,
                                        float bx, float by, float bz) {
  float dx = __fadd_rn(ax, -bx);
  float dy = __fadd_rn(ay, -by);
  float dz = __fadd_rn(az, -bz);
  return __fadd_rn(__fadd_rn(__fmul_rn(dx,dx), __fmul_rn(dy,dy)), __fmul_rn(dz,dz));
}

__device__ __forceinline__ int cell_of(float x, float y, float z) {
  int ix = min(7, max(0, (int)(x * 8.0f)));
  int iy = min(7, max(0, (int)(y * 8.0f)));
  int iz = min(7, max(0, (int)(z * 8.0f)));
  return (iz*8 + iy)*8 + ix;
}

// ---------------- prep: SoA xyz + cell id + counts, seed FPS step 0 ----------------
__global__ void k_build(const float* __restrict__ pcd_xyz,
                        const float* __restrict__ rgb_xyz) {
  int i = blockIdx.x*blockDim.x + threadIdx.x;
  if (i == 0) {
    g_gmax = 0u;
    g_ax[0] = pcd_xyz[0]; g_ay[0] = pcd_xyz[1]; g_az[0] = pcd_xyz[2];
  }
  if (i >= NTOT) return;
  float x, y, z;
  if (i < N_PCD) { x=pcd_xyz[i*3]; y=pcd_xyz[i*3+1]; z=pcd_xyz[i*3+2]; }
  else           { int j=i-N_PCD; x=rgb_xyz[j*3]; y=rgb_xyz[j*3+1]; z=rgb_xyz[j*3+2]; }
  g_xs[i]=x; g_ys[i]=y; g_zs[i]=z;
  int c = cell_of(x, y, z);
  g_cid[i] = c;
  atomicAdd(&g_ccnt[c], 1);
}

__global__ void k_cellscan() {   // one block, 512 threads: exclusive scan + reset counts
  __shared__ int s[NCELL];
  int t = threadIdx.x;
  int x = g_ccnt[t];
  s[t] = x;
  __syncthreads();
  for (int o = 1; o < NCELL; o <<= 1) {
    int u = (t >= o) ? s[t-o] : 0;
    __syncthreads();
    s[t] += u;
    __syncthreads();
  }
  int start = s[t] - x;
  g_cstart[t] = start;
  g_cfill[t]  = start;
  g_ccnt[t]   = 0;                 // reset for graph replay determinism
  if (t == NCELL-1) g_cstart[NCELL] = s[t];
}

__global__ void k_scatter() {
  int i = blockIdx.x*blockDim.x + threadIdx.x;
  if (i >= NTOT) return;
  int c = g_cid[i];
  int pos = atomicAdd(&g_cfill[c], 1);
  g_sp[pos] = make_float4(g_xs[i], g_ys[i], g_zs[i], __int_as_float(i));
}

// ---------------- FPS: single block, pruned cells, smem d[], packed-key argmax ----------------
__global__ void __launch_bounds__(1024, 1) k_fps4() {
  extern __shared__ float sd[];                   // NTOT floats: running min sq-dist (80KB)
  __shared__ unsigned long long s_key[NCELL];     // (vbits<<24)|((0x7fff-orig)<<9)|cell
  __shared__ float s_thr[NCELL];                  // prune threshold on dc2
  __shared__ float s_mx[NCELL], s_my[NCELL], s_mz[NCELL];
  __shared__ int   s_start[NCELL+1];
  __shared__ int   s_active[NCELL];
  __shared__ int   s_nact;
  __shared__ float s_center[3];
  __shared__ unsigned long long s_rk[16];

  int t = threadIdx.x;
  int lane = t & 31, w = t >> 5;

  for (int i = t; i < NTOT; i += 1024) sd[i] = 1e10f;
  if (t <= NCELL) s_start[t] = g_cstart[t];
  __syncthreads();
  if (t < NCELL) {
    int cnt = s_start[t+1] - s_start[t];
    s_thr[t] = (cnt > 0) ? 4e10f : -1.0f;   // nonempty: always active at step 1; empty: never
    s_key[t] = 0ull;
    s_mx[t]=0.f; s_my[t]=0.f; s_mz[t]=0.f;
  }
  if (t == 0) {
    s_center[0]=g_ax[0]; s_center[1]=g_ay[0]; s_center[2]=g_az[0];
    s_nact = 0;
  }
  __syncthreads();

  for (int step = 1; step < NA; step++) {
    float cx = s_center[0], cy = s_center[1], cz = s_center[2];

    // Phase A: prune test + ballot compaction (warps 0..15)
    if (t < NCELL) {
      int ix = t & 7, iy = (t >> 3) & 7, iz = t >> 6;
      float dc2 = sqdist((ix+0.5f)*0.125f, (iy+0.5f)*0.125f, (iz+0.5f)*0.125f,
                         cx, cy, cz);
      bool act = dc2 <= s_thr[t];
      unsigned m = __ballot_sync(0xffffffffu, act);
      int base = 0;
      if (lane == 0 && m) base = atomicAdd(&s_nact, __popc(m));
      base = __shfl_sync(0xffffffffu, base, 0);
      if (act) s_active[base + __popc(m & ((1u << lane) - 1u))] = t;
    }
    __syncthreads();
    int nact = s_nact;

    // Phase B: update active cells (all 32 warps, strided over active list)
    for (int j = w; j < nact; j += 32) {
      int cell = s_active[j];
      int st = s_start[cell], en = s_start[cell+1];
      unsigned long long bk = 0ull;     // (vbits<<32)|(0xffffffff-orig); 0 = empty lane
      float bx = 0.f, by = 0.f, bz = 0.f;
      float bv = 0.f;
      for (int p0 = st; p0 < en; p0 += 32) {
        int p = p0 + lane;
        if (p < en) {
          float4 q = __ldg(&g_sp[p]);
          float dd = sqdist(q.x, q.y, q.z, cx, cy, cz);
          float nd = fminf(sd[p], dd);
          sd[p] = nd;
          unsigned orig = (unsigned)__float_as_int(q.w);
          unsigned long long k = ((unsigned long long)__float_as_uint(nd) << 32)
                               | (0xffffffffu - orig);
          if (k > bk) { bk = k; bv = nd; bx = q.x; by = q.y; bz = q.z; }
        }
      }
      unsigned long long fk = bk;
#pragma unroll
      for (int o = 16; o; o >>= 1) {
        unsigned long long ok = __shfl_xor_sync(0xffffffffu, fk, o);
        if (ok > fk) fk = ok;
      }
      if (bk == fk && bk != 0ull) {     // exactly one winner (orig unique)
        unsigned orig = 0xffffffffu - (unsigned)(fk & 0xffffffffu);
        unsigned vb   = (unsigned)(fk >> 32);
        s_key[cell] = ((unsigned long long)vb << 24)
                    | ((unsigned long long)(0x7fffu - orig) << 9)
                    | (unsigned)cell;
        s_mx[cell] = bx; s_my[cell] = by; s_mz[cell] = bz;
        float r = CELL_R + __fsqrt_rn(bv);
        s_thr[cell] = __fmul_rn(r, r) * 1.0002f;
      }
    }
    __syncthreads();

    // Phase C: per-warp u64 max over 32 cells each (warps 0..15)
    if (t < NCELL) {
      unsigned long long k = s_key[t];
#pragma unroll
      for (int o = 16; o; o >>= 1) {
        unsigned long long ok = __shfl_xor_sync(0xffffffffu, k, o);
        if (ok > k) k = ok;
      }
      if (lane == 0) s_rk[w] = k;
    }
    __syncthreads();

    // Final: warp 0 reduces 16 keys, decodes cell, writes center, resets
    if (t < 32) {
      unsigned long long k = (lane < 16) ? s_rk[lane] : 0ull;
#pragma unroll
      for (int o = 8; o; o >>= 1) {
        unsigned long long ok = __shfl_xor_sync(0xffffffffu, k, o);
        if (ok > k) k = ok;
      }
      if (lane == 0) {
        int cell = (int)(k & 511ull);
        float bx = s_mx[cell], by = s_my[cell], bz = s_mz[cell];
        s_center[0]=bx; s_center[1]=by; s_center[2]=bz;
        g_ax[step]=bx; g_ay[step]=by; g_az[step]=bz;
        s_nact = 0;
      }
    }
    __syncthreads();
  }
}

// ---------------- merged weight transposes ----------------
__global__ void k_transW(const float* __restrict__ sa_W1, const float* __restrict__ sa_W2,
                         const float* __restrict__ sa_W3, const float* __restrict__ fp_W1,
                         const float* __restrict__ fp_W2) {
  int i = blockIdx.x*blockDim.x + threadIdx.x;
  if (i < 163*128) { int k=i>>7, n=i&127; g_W1T[i] = sa_W1[n*163+k]; return; }
  i -= 163*128;
  if (i < 128*128) { int k=i>>7, n=i&127; g_W2T[i] = sa_W2[n*128+k]; return; }
  i -= 128*128;
  if (i < 128*128) { int k=i>>7, n=i&127; g_W3T[i] = sa_W3[n*128+k]; return; }
  i -= 128*128;
  if (i < 160*128) { int k=i>>7, n=i&127; g_fpW1T[i] = fp_W1[n*288+k]; return; } // cols>=160 hit zeros
  i -= 160*128;
  if (i < 128*32)  { int k=i>>5, n=i&31;  g_fpW2T[i] = fp_W2[n*128+k]; return; }
}

// ---------------- rgb feature transpose, smem-tiled ----------------
__global__ void k_transRGB(const float* __restrict__ W) { // W: [128, 15000]
  __shared__ float tile[32][33];
  int kb = blockIdx.x * 32;
  int nb = blockIdx.y * 32;
  int tx = threadIdx.x, ty = threadIdx.y;   // 32 x 8
#pragma unroll
  for (int j = 0; j < 4; j++) {
    int n = nb + ty + j*8, k = kb + tx;
    tile[ty + j*8][tx] = (k < N_RGB) ? W[(size_t)n*N_RGB + k] : 0.f;
  }
  __syncthreads();
#pragma unroll
  for (int j = 0; j < 4; j++) {
    int k = kb + ty + j*8, n = nb + tx;
    if (k < N_RGB) g_rgbT[(size_t)k*128 + n] = tile[tx][ty + j*8];
  }
}

// ---------------- ball query: first-k in-radius by INDEX, pad with first ----------------
__global__ void k_ballq(int mode) {
  int w    = (blockIdx.x*blockDim.x + threadIdx.x) >> 5;
  int lane = threadIdx.x & 31;
  int npoints, ks; float r2, cx, cy, cz; int* row;
  if (mode == 0) {
    if (w >= NA) return;
    npoints = NTOT; ks = SA_NS; r2 = 0.01f;       // f32(0.1*0.1)
    cx = g_ax[w]; cy = g_ay[w]; cz = g_az[w];
    row = g_nb + (size_t)w*SA_NS;
  } else {
    if (w >= N_PCD) return;
    npoints = N_PCD; ks = NB_K; r2 = 0.04f;       // f32(0.2*0.2)
    cx = g_xs[w]; cy = g_ys[w]; cz = g_zs[w];
    row = g_nb2 + (size_t)w*NB_K;
  }
  int cnt = 0;
  for (int bs = 0; bs < npoints && cnt < ks; bs += 32) {
    int i = bs + lane;
    bool in = false;
    if (i < npoints) {
      float dd = sqdist(g_xs[i], g_ys[i], g_zs[i], cx, cy, cz);
      in = dd < r2;
    }
    unsigned m = __ballot_sync(0xffffffffu, in);
    if (m) {
      int rnk = __popc(m & ((1u << lane) - 1u));
      int pos = cnt + rnk;
      if (in && pos < ks) row[pos] = i;
      cnt += __popc(m);
    }
  }
  __syncwarp();
  if (cnt < ks) {               // center always in-radius -> cnt >= 1
    int first = row[0];
    for (int j = cnt + lane; j < ks; j += 32) row[j] = first;
  }
}

// ---------------- gather G = [gxyz | pcd_feat | rgb_feat] ----------------
__global__ void k_gather(const float* __restrict__ pcd_feat) {
  int r = blockIdx.x;
  int t = threadIdx.x;
  if (t >= K1) return;
  int a = r >> 5;
  int p = g_nb[r];
  float v;
  if (t < 3) {
    float pc = (t == 0) ? g_xs[p] : (t == 1) ? g_ys[p] : g_zs[p];
    float ac = (t == 0) ? g_ax[a] : (t == 1) ? g_ay[a] : g_az[a];
    v = __fadd_rn(pc, -ac) / 0.1f;
  } else if (t < 35) {
    v = (p < N_PCD) ? pcd_feat[p*32 + (t-3)] : 0.f;
  } else {
    v = (p >= N_PCD) ? g_rgbT[(size_t)(p - N_PCD)*128 + (t-35)] : 0.f;
  }
  g_G[(size_t)r*K1 + t] = v;
}

// ---------------- SGEMM + bias + relu: M=131072, N=128 ----------------
__global__ void __launch_bounds__(256, 2)
k_gemm(int layer, const float* __restrict__ b1,
       const float* __restrict__ b2, const float* __restrict__ b3) {
  const float* A; const float* Bt; const float* bias; float* C; int K;
  if (layer == 0)      { A=g_G;  Bt=g_W1T; bias=b1; C=g_H1; K=K1;  }
  else if (layer == 1) { A=g_H1; Bt=g_W2T; bias=b2; C=g_H2; K=128; }
  else                 { A=g_H2; Bt=g_W3T; bias=b3; C=g_H1; K=128; }

  __shared__ float As[8*132];
  __shared__ float Bs[8*128];
  int t  = threadIdx.x;
  int m0 = blockIdx.x * 128;
  int ty = t >> 4, tx = t & 15;
  float acc[8][8];
#pragma unroll
  for (int r = 0; r < 8; r++)
#pragma unroll
    for (int c = 0; c < 8; c++) acc[r][c] = 0.f;

  for (int k0 = 0; k0 < K; k0 += 8) {
#pragma unroll
    for (int i = 0; i < 4; i++) {
      int idx = t + i*256;
      int ml = idx >> 3, kk = idx & 7;
      int kg = k0 + kk;
      As[kk*132 + ml] = (kg < K) ? A[(size_t)(m0+ml)*K + kg] : 0.f;
    }
#pragma unroll
    for (int i = 0; i < 4; i++) {
      int idx = t + i*256;
      int kk = idx >> 7, n = idx & 127;
      int kg = k0 + kk;
      Bs[kk*128 + n] = (kg < K) ? Bt[(size_t)kg*128 + n] : 0.f;
    }
    __syncthreads();
#pragma unroll
    for (int kk = 0; kk < 8; kk++) {
      float4 a0 = *(const float4*)&As[kk*132 + ty*8];
      float4 a1 = *(const float4*)&As[kk*132 + ty*8 + 4];
      float4 b0 = *(const float4*)&Bs[kk*128 + tx*8];
      float4 b1 = *(const float4*)&Bs[kk*128 + tx*8 + 4];
      float a[8] = {a0.x,a0.y,a0.z,a0.w,a1.x,a1.y,a1.z,a1.w};
      float b[8] = {b0.x,b0.y,b0.z,b0.w,b1.x,b1.y,b1.z,b1.w};
#pragma unroll
      for (int r = 0; r < 8; r++)
#pragma unroll
        for (int c = 0; c < 8; c++) acc[r][c] = fmaf(a[r], b[c], acc[r][c]);
    }
    __syncthreads();
  }
#pragma unroll
  for (int r = 0; r < 8; r++) {
    int m = m0 + ty*8 + r;
#pragma unroll
    for (int c = 0; c < 8; c++) {
      int n = tx*8 + c;
      float v = acc[r][c] + bias[n];
      C[(size_t)m*128 + n] = v > 0.f ? v : 0.f;
    }
  }
}

__global__ void k_maxpool() {
  int a = blockIdx.x, c = threadIdx.x;
  const float* base = g_H1 + (size_t)a*SA_NS*128 + c;
  float m = base[0];
#pragma unroll 4
  for (int s = 1; s < SA_NS; s++) m = fmaxf(m, base[(size_t)s*128]);
  g_saf[a*128 + c] = m;
}

// ---------------- 3-NN among anchors + inverse-distance weights ----------------
__global__ void k_nn3() {
  int i = blockIdx.x*blockDim.x + threadIdx.x;
  if (i >= N_PCD) return;
  float px = g_xs[i], py = g_ys[i], pz = g_zs[i];
  float d0 = 1e30f, d1 = 1e30f, d2 = 1e30f;
  int   i0 = 0, i1 = 0, i2 = 0;
  for (int a = 0; a < NA; a++) {
    float dd = sqdist(px, py, pz, g_ax[a], g_ay[a], g_az[a]);
    if (dd < d2) {                 // strict: earlier index wins ties (lax.top_k stable)
      if (dd < d1) {
        d2 = d1; i2 = i1;
        if (dd < d0) { d1 = d0; i1 = i0; d0 = dd; i0 = a; }
        else         { d1 = dd; i1 = a; }
      } else { d2 = dd; i2 = a; }
    }
  }
  float w0 = 1.0f/(d0 + 1e-8f), w1 = 1.0f/(d1 + 1e-8f), w2 = 1.0f/(d2 + 1e-8f);
  float ws = (w0 + w1) + w2;
  g_nn[i*3+0]=i0; g_nn[i*3+1]=i1; g_nn[i*3+2]=i2;
  g_wg[i*3+0]=w0/ws; g_wg[i*3+1]=w1/ws; g_wg[i*3+2]=w2/ws;
}

// ---------------- fused FP MLP (5000 pcd rows; effective K=160) ----------------
__global__ void k_fp(const float* __restrict__ pcd_feat,
                     const float* __restrict__ b1, const float* __restrict__ b2,
                     float* __restrict__ out_vf) {
  __shared__ float s_in[128];
  __shared__ float s_pf[32];
  __shared__ float s_h[128];
  int n = blockIdx.x, t = threadIdx.x;
  int i0 = g_nn[n*3+0], i1 = g_nn[n*3+1], i2 = g_nn[n*3+2];
  float w0 = g_wg[n*3+0], w1 = g_wg[n*3+1], w2 = g_wg[n*3+2];
  s_in[t] = w0*g_saf[i0*128+t] + w1*g_saf[i1*128+t] + w2*g_saf[i2*128+t];
  if (t < 32) s_pf[t] = pcd_feat[n*32 + t];
  __syncthreads();
  float acc = b1[t];
#pragma unroll 8
  for (int k = 0; k < 128; k++) acc = fmaf(s_in[k], g_fpW1T[k*128 + t], acc);
#pragma unroll 8
  for (int k = 0; k < 32; k++)  acc = fmaf(s_pf[k], g_fpW1T[(128+k)*128 + t], acc);
  s_h[t] = acc > 0.f ? acc : 0.f;
  __syncthreads();
  if (t < 32) {
    float a2 = b2[t];
#pragma unroll 8
    for (int k = 0; k < 128; k++) a2 = fmaf(s_h[k], g_fpW2T[k*32 + t], a2);
    float v = a2 > 0.f ? a2 : 0.f;
    g_fpf[n*32 + t] = v;
    atomicMax(&g_gmax, __float_as_uint(v));     // relu>=0 -> uint order == float order
    float sq = v*v;
#pragma unroll
    for (int off = 16; off; off >>= 1) sq += __shfl_xor_sync(0xffffffffu, sq, off);
    float nrm = fmaxf(sqrtf(sq), 1e-12f);
    out_vf[n*32 + t] = v / nrm;
  }
}

// ---------------- detection scores ----------------
__global__ void k_det(float* __restrict__ out_scores) {
  int i = blockIdx.x, c = threadIdx.x;   // 32 threads = 32 channels
  const int* nb = g_nb2 + (size_t)i*NB_K;
  float sum = 0.f;
#pragma unroll 4
  for (int j = 0; j < NB_K; j++) sum += g_fpf[nb[j]*32 + c];
  float s = __uint_as_float(g_gmax) + 1e-6f;
  float fi = g_fpf[i*32 + c] / s;
  float mean = (sum * (1.0f/64.0f)) / s;
  float x = fi - mean;
  float lm = fmaxf(x, 0.f) + log1pf(expf(-fabsf(x)));   // softplus
  float dwmax = fi;
#pragma unroll
  for (int off = 16; off; off >>= 1) dwmax = fmaxf(dwmax, __shfl_xor_sync(0xffffffffu, dwmax, off));
  float sc = lm * (fi / (1e-6f + dwmax));
#pragma unroll
  for (int off = 16; off; off >>= 1) sc = fmaxf(sc, __shfl_xor_sync(0xffffffffu, sc, off));
  if (c == 0) out_scores[i] = sc;
}

__global__ void k_out(const float* __restrict__ pcd_xyz, float* __restrict__ out) {
  int i = blockIdx.x*blockDim.x + threadIdx.x;
  if (i < N_PCD*3) out[i] = pcd_xyz[i];
}

extern "C" void kernel_launch(void* const* d_in, const int* in_sizes, int n_in,
                              void* d_out, int out_size) {
  (void)in_sizes; (void)n_in; (void)out_size;
  const float* pcd_xyz   = (const float*)d_in[0];
  const float* pcd_feat  = (const float*)d_in[1];
  const float* rgb_xyz   = (const float*)d_in[2];
  const float* rgb_feats = (const float*)d_in[3];
  const float* sa_W1 = (const float*)d_in[4];
  const float* sa_b1 = (const float*)d_in[5];
  const float* sa_W2 = (const float*)d_in[6];
  const float* sa_b2 = (const float*)d_in[7];
  const float* sa_W3 = (const float*)d_in[8];
  const float* sa_b3 = (const float*)d_in[9];
  const float* fp_W1 = (const float*)d_in[10];
  const float* fp_b1 = (const float*)d_in[11];
  const float* fp_W2 = (const float*)d_in[12];
  const float* fp_b2 = (const float*)d_in[13];
  float* out = (float*)d_out;
  float* out_scores = out + N_PCD*3;          // 15000..20000
  float* out_vf     = out + N_PCD*3 + N_PCD;  // 20000..180000

  static int smem_set = 0;
  if (!smem_set) {
    cudaFuncSetAttribute(k_fps4, cudaFuncAttributeMaxDynamicSharedMemorySize,
                         NTOT*(int)sizeof(float));
    smem_set = 1;
  }

  k_build<<<(NTOT+255)/256, 256>>>(pcd_xyz, rgb_xyz);           // 0
  k_cellscan<<<1, NCELL>>>();                                    // 1
  k_scatter<<<(NTOT+255)/256, 256>>>();                          // 2
  k_fps4<<<1, 1024, NTOT*sizeof(float)>>>();                     // 3  (ncu profiles this slot)
  k_transW<<<(78208+255)/256, 256>>>(sa_W1, sa_W2, sa_W3, fp_W1, fp_W2);
  { dim3 g((N_RGB+31)/32, 4), b(32, 8); k_transRGB<<<g, b>>>(rgb_feats); }
  k_ballq<<<(NA*32+255)/256, 256>>>(0);
  k_gather<<<NROWS, 192>>>(pcd_feat);
  k_gemm<<<NROWS/128, 256>>>(0, sa_b1, sa_b2, sa_b3);
  k_gemm<<<NROWS/128, 256>>>(1, sa_b1, sa_b2, sa_b3);
  k_gemm<<<NROWS/128, 256>>>(2, sa_b1, sa_b2, sa_b3);
  k_maxpool<<<NA, 128>>>();
  k_nn3<<<(N_PCD+255)/256, 256>>>();
  k_fp<<<N_PCD, 128>>>(pcd_feat, fp_b1, fp_b2, out_vf);
  k_ballq<<<(N_PCD*32+255)/256, 256>>>(1);
  k_det<<<N_PCD, 32>>>(out_scores);
  k_out<<<(N_PCD*3+255)/256, 256>>>(pcd_xyz, out);
}